// round 12
// baseline (speedup 1.0000x reference)
#include <cuda_runtime.h>
#include <cuda_bf16.h>
#include <math.h>
#include <stdint.h>

// ---------------- problem constants ----------------
#define BATCH   2
#define SEQL    2048
#define DMODEL  1024
#define DSTATE  16
#define DINNER  2048
#define NROWS   (BATCH * SEQL)   // 4096

// ---------------- scratch (static device globals; no allocation) ----------------
__device__ float g_xz[NROWS * 2 * DINNER];     // (xa | z)
__device__ float g_xc[NROWS * DINNER];         // conv+silu
__device__ float g_bc[NROWS * 32];             // [B_ssm(16) | C_ssm(16)] per row
__device__ float g_gg[NROWS * DINNER];         // scan output, tf32, K-PERMUTED
__device__ float g_xr[NROWS * DMODEL];         // x, tf32, K-PERMUTED
__device__ float g_wt_in[2 * DINNER * DMODEL]; // W_in^T [4096][1024], tf32, K-perm
__device__ float g_wt_out[DMODEL * DINNER];    // W_out^T [1024][2048], tf32, K-perm

// ---------------- helpers ----------------
__device__ __forceinline__ void cpasync16(void* dst, const void* src) {
    uint32_t d = (uint32_t)__cvta_generic_to_shared(dst);
    asm volatile("cp.async.cg.shared.global [%0], [%1], 16;\n" :: "r"(d), "l"(src));
}
#define CP_COMMIT() asm volatile("cp.async.commit_group;\n" ::: "memory")
#define CP_WAIT1()  asm volatile("cp.async.wait_group 1;\n" ::: "memory")
#define CP_WAIT0()  asm volatile("cp.async.wait_group 0;\n" ::: "memory")

__device__ __forceinline__ float round_tf32(float x) {
    uint32_t r;
    asm("cvt.rna.tf32.f32 %0, %1;" : "=r"(r) : "f"(x));
    return __uint_as_float(r);
}
// position of original k inside the permuted 8-group: 0,4,1,5,2,6,3,7
__device__ __forceinline__ int kperm_pos(int k) {
    return (k & ~7) | ((k & 4) ? (((k & 3) << 1) | 1) : ((k & 3) << 1));
}

// =======================================================================
// TF32 mma.sync GEMM, 3-STAGE cp.async pipeline (dynamic smem).
// K-PERMUTED operands, B pre-transposed to [N,K]. CTA TM x 128 x 16,
// 128 thr = 4 warps (2x2). Fragment loads are LDS.64.
// Stage for chunk kt+2 reuses chunk kt-1's stage: all warps finished
// reading it before the __syncthreads() of iteration kt.
// =======================================================================
#define SSTR 24

template<int TM>
__global__ __launch_bounds__(128)
void tf32gemm_kernel(const float* __restrict__ A, const float* __restrict__ Bt,
                     float* __restrict__ C, int M, int N, int K)
{
    constexpr int WM = TM / 2;
    constexpr int MT = TM / 32;
    constexpr int STAGE = (TM + 128) * SSTR;   // floats per stage

    extern __shared__ float sm[];

    const int tid  = threadIdx.x;
    const int warp = tid >> 5;
    const int lane = tid & 31;
    const int wm   = warp >> 1;
    const int wn   = warp & 1;
    const int g    = lane >> 2;
    const int t    = lane & 3;

    const int m0 = blockIdx.y * TM;
    const int n0 = blockIdx.x * 128;

    float acc[MT][8][4];
    #pragma unroll
    for (int i = 0; i < MT; i++)
        #pragma unroll
        for (int j = 0; j < 8; j++)
            #pragma unroll
            for (int v = 0; v < 4; v++) acc[i][j][v] = 0.f;

    #define LOAD_CHUNK(kt, st) do {                                            \
        float* As_ = sm + (st) * STAGE;                                        \
        float* Bs_ = As_ + TM * SSTR;                                          \
        _Pragma("unroll")                                                      \
        for (int it = 0; it < TM / 32; it++) {                                 \
            int id = it * 128 + tid;                                           \
            int row = id >> 2, seg = (id & 3) * 4;                             \
            cpasync16(&As_[row * SSTR + seg],                                  \
                      A + (size_t)(m0 + row) * K + (kt) * 16 + seg);           \
        }                                                                      \
        _Pragma("unroll")                                                      \
        for (int it = 0; it < 4; it++) {                                       \
            int id = it * 128 + tid;                                           \
            int row = id >> 2, seg = (id & 3) * 4;                             \
            cpasync16(&Bs_[row * SSTR + seg],                                  \
                      Bt + (size_t)(n0 + row) * K + (kt) * 16 + seg);          \
        }                                                                      \
        CP_COMMIT();                                                           \
    } while (0)

    const int nk = K / 16;

    LOAD_CHUNK(0, 0);
    if (nk > 1) LOAD_CHUNK(1, 1);

    for (int kt = 0; kt < nk; kt++) {
        const int cur = kt % 3;
        // outstanding groups here are a subset of {kt, kt+1}; ensure kt landed
        if (kt + 1 < nk) CP_WAIT1(); else CP_WAIT0();
        __syncthreads();
        if (kt + 2 < nk)
            LOAD_CHUNK(kt + 2, (kt + 2) % 3);

        const float* As_ = sm + cur * STAGE;
        const float* Bs_ = As_ + TM * SSTR;

        #pragma unroll
        for (int kk = 0; kk < 16; kk += 8) {
            float2 av0[MT], av1[MT], bv[8];
            #pragma unroll
            for (int mt = 0; mt < MT; mt++) {
                const int mr = wm * WM + mt * 16 + g;
                av0[mt] = *(const float2*)&As_[mr * SSTR + kk + 2 * t];
                av1[mt] = *(const float2*)&As_[(mr + 8) * SSTR + kk + 2 * t];
            }
            #pragma unroll
            for (int nt = 0; nt < 8; nt++) {
                const int nr = wn * 64 + nt * 8 + g;
                bv[nt] = *(const float2*)&Bs_[nr * SSTR + kk + 2 * t];
            }
            #pragma unroll
            for (int mt = 0; mt < MT; mt++)
                #pragma unroll
                for (int nt = 0; nt < 8; nt++) {
                    float* c = acc[mt][nt];
                    asm volatile(
                        "mma.sync.aligned.m16n8k8.row.col.f32.tf32.tf32.f32 "
                        "{%0,%1,%2,%3}, {%4,%5,%6,%7}, {%8,%9}, {%0,%1,%2,%3};\n"
                        : "+f"(c[0]), "+f"(c[1]), "+f"(c[2]), "+f"(c[3])
                        : "r"(__float_as_uint(av0[mt].x)), "r"(__float_as_uint(av1[mt].x)),
                          "r"(__float_as_uint(av0[mt].y)), "r"(__float_as_uint(av1[mt].y)),
                          "r"(__float_as_uint(bv[nt].x)),  "r"(__float_as_uint(bv[nt].y)));
                }
        }
    }
    #undef LOAD_CHUNK

    #pragma unroll
    for (int mt = 0; mt < MT; mt++) {
        #pragma unroll
        for (int nt = 0; nt < 8; nt++) {
            const size_t row = (size_t)m0 + wm * WM + mt * 16 + g;
            const int    col = n0 + wn * 64 + nt * 8 + 2 * t;
            *(float2*)(C + row * N + col)       = make_float2(acc[mt][nt][0], acc[mt][nt][1]);
            *(float2*)(C + (row + 8) * N + col) = make_float2(acc[mt][nt][2], acc[mt][nt][3]);
        }
    }
}

// ---------------- round + K-permute (linear, rows are multiples of 8) ----------
__global__ void round_perm_kernel(const float* __restrict__ in,
                                  float* __restrict__ out, int n8)
{
    int i = blockIdx.x * blockDim.x + threadIdx.x;
    if (i >= n8) return;
    float4 v0 = ((const float4*)in)[2 * i];
    float4 v1 = ((const float4*)in)[2 * i + 1];
    float4 o0, o1;
    o0.x = round_tf32(v0.x); o0.y = round_tf32(v1.x);
    o0.z = round_tf32(v0.y); o0.w = round_tf32(v1.y);
    o1.x = round_tf32(v0.z); o1.y = round_tf32(v1.z);
    o1.z = round_tf32(v0.w); o1.w = round_tf32(v1.w);
    ((float4*)out)[2 * i]     = o0;
    ((float4*)out)[2 * i + 1] = o1;
}

// ---------------- transpose + round + K-permute: out[n][P(k)] = in[k][n] -------
__global__ void transpose_rp_kernel(const float* __restrict__ in,
                                    float* __restrict__ out, int R, int C)
{
    __shared__ float tb[32][33];
    int c0 = blockIdx.x * 32, r0 = blockIdx.y * 32;
    int x = threadIdx.x, y = threadIdx.y;    // 32 x 8
    #pragma unroll
    for (int i = 0; i < 32; i += 8)
        tb[y + i][x] = in[(size_t)(r0 + y + i) * C + c0 + x];
    __syncthreads();
    int kp = kperm_pos(r0 + x);
    #pragma unroll
    for (int i = 0; i < 32; i += 8)
        out[(size_t)(c0 + y + i) * R + kp] = round_tf32(tb[x][y + i]);
}

// ---------------- depthwise causal conv (D_CONV=4) + bias + SiLU ----------------
__global__ void conv_silu_kernel(const float* __restrict__ xz,
                                 const float* __restrict__ cw,
                                 const float* __restrict__ cb,
                                 float* __restrict__ xc)
{
    int idx = blockIdx.x * blockDim.x + threadIdx.x;
    if (idx >= NROWS * DINNER) return;
    int d  = idx & (DINNER - 1);
    int bl = idx >> 11;
    int l  = bl & (SEQL - 1);
    int b  = bl >> 11;

    float acc = cb[d];
    const float w0 = cw[d * 4 + 0], w1 = cw[d * 4 + 1],
                w2 = cw[d * 4 + 2], w3 = cw[d * 4 + 3];
    const float* base = xz + ((size_t)b * SEQL) * (2 * DINNER) + d;
    if (l >= 3) acc = fmaf(w0, base[(size_t)(l - 3) * (2 * DINNER)], acc);
    if (l >= 2) acc = fmaf(w1, base[(size_t)(l - 2) * (2 * DINNER)], acc);
    if (l >= 1) acc = fmaf(w2, base[(size_t)(l - 1) * (2 * DINNER)], acc);
    acc = fmaf(w3, base[(size_t)l * (2 * DINNER)], acc);

    float sig = 1.f / (1.f + __expf(-acc));
    xc[idx] = acc * sig;
}

// ---------------- BC = xc @ W_xproj : 16 rows per block, row-major out ---------
__global__ __launch_bounds__(256)
void xproj_kernel(const float* __restrict__ xc,
                  const float* __restrict__ W,   // [DINNER,32]
                  float* __restrict__ bc)        // [NROWS][32]
{
    const int r0 = blockIdx.x * 16;
    const int c  = threadIdx.x & 31;
    const int st = threadIdx.x >> 5;    // 0..7
    const float* x0 = xc + (size_t)r0 * DINNER;

    float acc[16];
    #pragma unroll
    for (int r = 0; r < 16; r++) acc[r] = 0.f;

    for (int k = st; k < DINNER; k += 8) {
        float wv = W[k * 32 + c];
        #pragma unroll
        for (int r = 0; r < 16; r++)
            acc[r] = fmaf(x0[(size_t)r * DINNER + k], wv, acc[r]);
    }

    __shared__ float red[8][16][32];
    #pragma unroll
    for (int r = 0; r < 16; r++) red[st][r][c] = acc[r];
    __syncthreads();

    for (int o = threadIdx.x; o < 512; o += 256) {
        int rr = o >> 5, cc = o & 31;
        float s = 0.f;
        #pragma unroll
        for (int i = 0; i < 8; i++) s += red[i][rr][cc];
        bc[(size_t)(r0 + rr) * 32 + cc] = s;
    }
}

// ---------------- selective scan: 8 lanes x 2 states per (b,d) channel ----------
// (unchanged from R10 — measured win)
#define UNR 8
__global__ __launch_bounds__(256)
void scan_kernel(const float* __restrict__ xc,
                 const float* __restrict__ bc,     // [NROWS][32]
                 const float* __restrict__ A_log,  // [DINNER][16]
                 const float* __restrict__ Dvec,
                 const float* __restrict__ xz,
                 const float* __restrict__ Wdt,    // [16, DINNER]
                 const float* __restrict__ bdt,
                 float* __restrict__ g)
{
    int gid = blockIdx.x * blockDim.x + threadIdx.x;   // BATCH*DINNER*8
    int j   = gid & 7;
    int ch  = gid >> 3;
    int d   = ch & (DINNER - 1);
    int b   = ch >> 11;
    int s0  = 2 * j;

    float2 al = *(const float2*)&A_log[d * DSTATE + s0];
    const float a0 = -expf(al.x);
    const float a1 = -expf(al.y);
    const float Dd    = Dvec[d];
    const float wdt0  = Wdt[s0 * DINNER + d];
    const float wdt1  = Wdt[(s0 + 1) * DINNER + d];
    const float bdt_d = bdt[d];

    const float* xptr = xc + (size_t)b * SEQL * DINNER + d;
    const float* zptr = xz + (size_t)b * SEQL * (2 * DINNER) + DINNER + d;
    const float* bcb  = bc + (size_t)b * SEQL * 32;
    float*       gptr = g  + (size_t)b * SEQL * DINNER + kperm_pos(d);

    float h0 = 0.f, h1 = 0.f;
    for (int l0 = 0; l0 < SEQL; l0 += UNR) {
        float  bxt[UNR], bzv[UNR];
        float2 bB[UNR], bC[UNR];
        #pragma unroll
        for (int i = 0; i < UNR; i++) {
            bxt[i] = xptr[(size_t)(l0 + i) * DINNER];
            bzv[i] = zptr[(size_t)(l0 + i) * (2 * DINNER)];
            bB[i]  = *(const float2*)&bcb[(l0 + i) * 32 + s0];
            bC[i]  = *(const float2*)&bcb[(l0 + i) * 32 + 16 + s0];
        }
        float dA0[UNR], dA1[UNR], w0[UNR], w1[UNR];
        #pragma unroll
        for (int i = 0; i < UNR; i++) {
            float pd = fmaf(bB[i].x, wdt0, bB[i].y * wdt1);
            pd += __shfl_xor_sync(0xffffffffu, pd, 1);
            pd += __shfl_xor_sync(0xffffffffu, pd, 2);
            pd += __shfl_xor_sync(0xffffffffu, pd, 4);
            float dl  = pd + bdt_d;
            float dtv = (dl > 20.f) ? dl : __logf(1.f + __expf(dl));
            dA0[i] = __expf(dtv * a0);
            dA1[i] = __expf(dtv * a1);
            float dx = dtv * bxt[i];
            w0[i] = dx * bB[i].x;
            w1[i] = dx * bB[i].y;
        }
        float p[UNR];
        #pragma unroll
        for (int i = 0; i < UNR; i++) {
            h0 = fmaf(dA0[i], h0, w0[i]);
            h1 = fmaf(dA1[i], h1, w1[i]);
            p[i] = fmaf(h0, bC[i].x, h1 * bC[i].y);
        }
        #pragma unroll
        for (int i = 0; i < UNR; i++) {
            p[i] += __shfl_xor_sync(0xffffffffu, p[i], 4);
            p[i] += __shfl_xor_sync(0xffffffffu, p[i], 2);
            p[i] += __shfl_xor_sync(0xffffffffu, p[i], 1);
        }
        if (j == 0) {
            #pragma unroll
            for (int i = 0; i < UNR; i++) {
                float y   = fmaf(Dd, bxt[i], p[i]);
                float z   = bzv[i];
                float sig = 1.f / (1.f + __expf(-z));
                gptr[(size_t)(l0 + i) * DINNER] = round_tf32(y * (z * sig));
            }
        }
    }
}

// ---------------- launch ----------------
extern "C" void kernel_launch(void* const* d_in, const int* in_sizes, int n_in,
                              void* d_out, int out_size)
{
    const float* x      = (const float*)d_in[0];
    const float* W_in   = (const float*)d_in[1];
    const float* conv_w = (const float*)d_in[2];
    const float* conv_b = (const float*)d_in[3];
    const float* W_xprj = (const float*)d_in[4];
    const float* W_dt   = (const float*)d_in[5];
    const float* b_dt   = (const float*)d_in[6];
    const float* A_log  = (const float*)d_in[7];
    const float* Dvec   = (const float*)d_in[8];
    const float* W_out  = (const float*)d_in[9];
    float* out = (float*)d_out;

    float *xz, *xc, *bc, *gg, *xr, *wt_in, *wt_out;
    cudaGetSymbolAddress((void**)&xz, g_xz);
    cudaGetSymbolAddress((void**)&xc, g_xc);
    cudaGetSymbolAddress((void**)&bc, g_bc);
    cudaGetSymbolAddress((void**)&gg, g_gg);
    cudaGetSymbolAddress((void**)&xr, g_xr);
    cudaGetSymbolAddress((void**)&wt_in, g_wt_in);
    cudaGetSymbolAddress((void**)&wt_out, g_wt_out);

    // dynamic smem sizes: 3 stages x (TM+128)*SSTR floats
    const int smem128 = 3 * (128 + 128) * SSTR * 4;   // 73728
    const int smem64  = 3 * (64 + 128) * SSTR * 4;    // 55296
    cudaFuncSetAttribute(tf32gemm_kernel<128>,
                         cudaFuncAttributeMaxDynamicSharedMemorySize, smem128);
    cudaFuncSetAttribute(tf32gemm_kernel<64>,
                         cudaFuncAttributeMaxDynamicSharedMemorySize, smem64);

    // 0) preprocess operands: round to tf32, transpose weights to [N,K], permute K
    {
        int n8 = (NROWS * DMODEL) / 8;
        round_perm_kernel<<<(n8 + 255) / 256, 256>>>(x, xr, n8);
        dim3 blk(32, 8);
        transpose_rp_kernel<<<dim3((2 * DINNER) / 32, DMODEL / 32), blk>>>(W_in, wt_in, DMODEL, 2 * DINNER);
        transpose_rp_kernel<<<dim3(DMODEL / 32, DINNER / 32), blk>>>(W_out, wt_out, DINNER, DMODEL);
    }
    // 1) xz = x @ W_in   (M=4096, N=4096, K=1024), 128-row tiles
    {
        dim3 grid((2 * DINNER) / 128, NROWS / 128);
        tf32gemm_kernel<128><<<grid, 128, smem128>>>(xr, wt_in, xz, NROWS, 2 * DINNER, DMODEL);
    }
    // 2) conv + SiLU
    {
        int total = NROWS * DINNER;
        conv_silu_kernel<<<(total + 255) / 256, 256>>>(xz, conv_w, conv_b, xc);
    }
    // 3) BC = xc @ W_xproj (16 rows/block)
    xproj_kernel<<<NROWS / 16, 256>>>(xc, W_xprj, bc);
    // 4) scan (delta fused, +D, +gate, tf32 + K-permuted output), 8 lanes/channel
    {
        int total = BATCH * DINNER * 8;   // 32768
        scan_kernel<<<total / 256, 256>>>(xc, bc, A_log, Dvec, xz, W_dt, b_dt, gg);
    }
    // 5) out = g @ W_out  (M=4096, N=1024, K=2048), 64-row tiles for 512 CTAs
    {
        dim3 grid(DMODEL / 128, NROWS / 64);
        tf32gemm_kernel<64><<<grid, 128, smem64>>>(gg, wt_out, out, NROWS, DMODEL, DINNER);
    }
}

// round 13
// speedup vs baseline: 1.1543x; 1.1543x over previous
#include <cuda_runtime.h>
#include <cuda_bf16.h>
#include <math.h>
#include <stdint.h>

// ---------------- problem constants ----------------
#define BATCH   2
#define SEQL    2048
#define DMODEL  1024
#define DSTATE  16
#define DINNER  2048
#define NROWS   (BATCH * SEQL)   // 4096

// ---------------- scratch (static device globals; no allocation) ----------------
__device__ float g_xz[NROWS * 2 * DINNER];     // (xa | z)
__device__ float g_xc[NROWS * DINNER];         // conv+silu
__device__ float g_bc[NROWS * 32];             // [B_ssm(16) | C_ssm(16)] per row
__device__ float g_gg[NROWS * DINNER];         // scan output, tf32, K-PERMUTED
__device__ float g_xr[NROWS * DMODEL];         // x, tf32, K-PERMUTED
__device__ float g_wt_in[2 * DINNER * DMODEL]; // W_in^T [4096][1024], tf32, K-perm
__device__ float g_wt_out[DMODEL * DINNER];    // W_out^T [1024][2048], tf32, K-perm

// ---------------- helpers ----------------
__device__ __forceinline__ void cpasync16(void* dst, const void* src) {
    uint32_t d = (uint32_t)__cvta_generic_to_shared(dst);
    asm volatile("cp.async.cg.shared.global [%0], [%1], 16;\n" :: "r"(d), "l"(src));
}
#define CP_COMMIT() asm volatile("cp.async.commit_group;\n" ::: "memory")
#define CP_WAIT0()  asm volatile("cp.async.wait_group 0;\n" ::: "memory")

__device__ __forceinline__ float round_tf32(float x) {
    uint32_t r;
    asm("cvt.rna.tf32.f32 %0, %1;" : "=r"(r) : "f"(x));
    return __uint_as_float(r);
}
// position of original k inside the permuted 8-group: 0,4,1,5,2,6,3,7
__device__ __forceinline__ int kperm_pos(int k) {
    return (k & ~7) | ((k & 4) ? (((k & 3) << 1) | 1) : ((k & 3) << 1));
}

// =======================================================================
// TF32 mma.sync GEMM — R10 baseline (measured: GEMM1 228us, tensor 56.6%).
// 2-stage static-smem pipeline; K-PERMUTED operands; B pre-transposed.
// CTA TM x 128 x 16, 128 thr = 4 warps (2x2). Fragment loads are LDS.64.
// =======================================================================
#define SSTR 24

template<int TM>
__global__ __launch_bounds__(128)
void tf32gemm_kernel(const float* __restrict__ A, const float* __restrict__ Bt,
                     float* __restrict__ C, int M, int N, int K)
{
    constexpr int WM = TM / 2;
    constexpr int MT = TM / 32;

    __shared__ float As[2][TM][SSTR];
    __shared__ float Bs[2][128][SSTR];

    const int tid  = threadIdx.x;
    const int warp = tid >> 5;
    const int lane = tid & 31;
    const int wm   = warp >> 1;
    const int wn   = warp & 1;
    const int g    = lane >> 2;
    const int t    = lane & 3;

    const int m0 = blockIdx.y * TM;
    const int n0 = blockIdx.x * 128;

    float acc[MT][8][4];
    #pragma unroll
    for (int i = 0; i < MT; i++)
        #pragma unroll
        for (int j = 0; j < 8; j++)
            #pragma unroll
            for (int v = 0; v < 4; v++) acc[i][j][v] = 0.f;

    #define LOAD_CHUNK(kt, st) do {                                            \
        _Pragma("unroll")                                                      \
        for (int it = 0; it < TM / 32; it++) {                                 \
            int id = it * 128 + tid;                                           \
            int row = id >> 2, seg = (id & 3) * 4;                             \
            cpasync16(&As[st][row][seg],                                       \
                      A + (size_t)(m0 + row) * K + (kt) * 16 + seg);           \
        }                                                                      \
        _Pragma("unroll")                                                      \
        for (int it = 0; it < 4; it++) {                                       \
            int id = it * 128 + tid;                                           \
            int row = id >> 2, seg = (id & 3) * 4;                             \
            cpasync16(&Bs[st][row][seg],                                       \
                      Bt + (size_t)(n0 + row) * K + (kt) * 16 + seg);          \
        }                                                                      \
        CP_COMMIT();                                                           \
    } while (0)

    const int nk = K / 16;

    LOAD_CHUNK(0, 0);

    for (int kt = 0; kt < nk; kt++) {
        const int cur = kt & 1;
        CP_WAIT0();
        __syncthreads();
        if (kt + 1 < nk)
            LOAD_CHUNK(kt + 1, cur ^ 1);

        #pragma unroll
        for (int kk = 0; kk < 16; kk += 8) {
            float2 av0[MT], av1[MT], bv[8];
            #pragma unroll
            for (int mt = 0; mt < MT; mt++) {
                const int mr = wm * WM + mt * 16 + g;
                av0[mt] = *(const float2*)&As[cur][mr][kk + 2 * t];
                av1[mt] = *(const float2*)&As[cur][mr + 8][kk + 2 * t];
            }
            #pragma unroll
            for (int nt = 0; nt < 8; nt++) {
                const int nr = wn * 64 + nt * 8 + g;
                bv[nt] = *(const float2*)&Bs[cur][nr][kk + 2 * t];
            }
            #pragma unroll
            for (int mt = 0; mt < MT; mt++)
                #pragma unroll
                for (int nt = 0; nt < 8; nt++) {
                    float* c = acc[mt][nt];
                    asm volatile(
                        "mma.sync.aligned.m16n8k8.row.col.f32.tf32.tf32.f32 "
                        "{%0,%1,%2,%3}, {%4,%5,%6,%7}, {%8,%9}, {%0,%1,%2,%3};\n"
                        : "+f"(c[0]), "+f"(c[1]), "+f"(c[2]), "+f"(c[3])
                        : "r"(__float_as_uint(av0[mt].x)), "r"(__float_as_uint(av1[mt].x)),
                          "r"(__float_as_uint(av0[mt].y)), "r"(__float_as_uint(av1[mt].y)),
                          "r"(__float_as_uint(bv[nt].x)),  "r"(__float_as_uint(bv[nt].y)));
                }
        }
    }
    #undef LOAD_CHUNK

    #pragma unroll
    for (int mt = 0; mt < MT; mt++) {
        #pragma unroll
        for (int nt = 0; nt < 8; nt++) {
            const size_t row = (size_t)m0 + wm * WM + mt * 16 + g;
            const int    col = n0 + wn * 64 + nt * 8 + 2 * t;
            *(float2*)(C + row * N + col)       = make_float2(acc[mt][nt][0], acc[mt][nt][1]);
            *(float2*)(C + (row + 8) * N + col) = make_float2(acc[mt][nt][2], acc[mt][nt][3]);
        }
    }
}

// ---------------- round + K-permute (linear, rows are multiples of 8) ----------
__global__ void round_perm_kernel(const float* __restrict__ in,
                                  float* __restrict__ out, int n8)
{
    int i = blockIdx.x * blockDim.x + threadIdx.x;
    if (i >= n8) return;
    float4 v0 = ((const float4*)in)[2 * i];
    float4 v1 = ((const float4*)in)[2 * i + 1];
    float4 o0, o1;
    o0.x = round_tf32(v0.x); o0.y = round_tf32(v1.x);
    o0.z = round_tf32(v0.y); o0.w = round_tf32(v1.y);
    o1.x = round_tf32(v0.z); o1.y = round_tf32(v1.z);
    o1.z = round_tf32(v0.w); o1.w = round_tf32(v1.w);
    ((float4*)out)[2 * i]     = o0;
    ((float4*)out)[2 * i + 1] = o1;
}

// ---------------- transpose + round + K-permute: out[n][P(k)] = in[k][n] -------
__global__ void transpose_rp_kernel(const float* __restrict__ in,
                                    float* __restrict__ out, int R, int C)
{
    __shared__ float tb[32][33];
    int c0 = blockIdx.x * 32, r0 = blockIdx.y * 32;
    int x = threadIdx.x, y = threadIdx.y;    // 32 x 8
    #pragma unroll
    for (int i = 0; i < 32; i += 8)
        tb[y + i][x] = in[(size_t)(r0 + y + i) * C + c0 + x];
    __syncthreads();
    int kp = kperm_pos(r0 + x);
    #pragma unroll
    for (int i = 0; i < 32; i += 8)
        out[(size_t)(c0 + y + i) * R + kp] = round_tf32(tb[x][y + i]);
}

// ---------------- depthwise causal conv (D_CONV=4) + bias + SiLU ----------------
__global__ void conv_silu_kernel(const float* __restrict__ xz,
                                 const float* __restrict__ cw,
                                 const float* __restrict__ cb,
                                 float* __restrict__ xc)
{
    int idx = blockIdx.x * blockDim.x + threadIdx.x;
    if (idx >= NROWS * DINNER) return;
    int d  = idx & (DINNER - 1);
    int bl = idx >> 11;
    int l  = bl & (SEQL - 1);
    int b  = bl >> 11;

    float acc = cb[d];
    const float w0 = cw[d * 4 + 0], w1 = cw[d * 4 + 1],
                w2 = cw[d * 4 + 2], w3 = cw[d * 4 + 3];
    const float* base = xz + ((size_t)b * SEQL) * (2 * DINNER) + d;
    if (l >= 3) acc = fmaf(w0, base[(size_t)(l - 3) * (2 * DINNER)], acc);
    if (l >= 2) acc = fmaf(w1, base[(size_t)(l - 2) * (2 * DINNER)], acc);
    if (l >= 1) acc = fmaf(w2, base[(size_t)(l - 1) * (2 * DINNER)], acc);
    acc = fmaf(w3, base[(size_t)l * (2 * DINNER)], acc);

    float sig = 1.f / (1.f + __expf(-acc));
    xc[idx] = acc * sig;
}

// ---------------- BC = xc @ W_xproj : 4 rows per block (R7/R10 layout) ---------
__global__ void xproj_kernel(const float* __restrict__ xc,
                             const float* __restrict__ W,   // [DINNER,32]
                             float* __restrict__ bc)        // [NROWS][32]
{
    const int r0 = blockIdx.x * 4;
    const int c  = threadIdx.x & 31;
    const int st = threadIdx.x >> 5;
    const float* x0 = xc + (size_t)r0 * DINNER;

    float a0 = 0.f, a1 = 0.f, a2 = 0.f, a3 = 0.f;
    for (int k = st; k < DINNER; k += 8) {
        float wv = W[k * 32 + c];
        a0 = fmaf(x0[k],              wv, a0);
        a1 = fmaf(x0[DINNER + k],     wv, a1);
        a2 = fmaf(x0[2 * DINNER + k], wv, a2);
        a3 = fmaf(x0[3 * DINNER + k], wv, a3);
    }

    __shared__ float red[8][4][32];
    red[st][0][c] = a0; red[st][1][c] = a1;
    red[st][2][c] = a2; red[st][3][c] = a3;
    __syncthreads();
    if (threadIdx.x < 128) {
        int rc = threadIdx.x & 31;
        int rr = threadIdx.x >> 5;
        float s = 0.f;
        #pragma unroll
        for (int i = 0; i < 8; i++) s += red[i][rr][rc];
        bc[(size_t)(r0 + rr) * 32 + rc] = s;
    }
}

// ---------------- selective scan: 4 lanes x 4 states per (b,d) channel ----------
// Lane j owns states 4j..4j+3 (B/C load as float4). Butterflies are 2-deep.
// Each warp covers 8 channels. Output written K-PERMUTED for GEMM2.
#define UNR 8
__global__ __launch_bounds__(256)
void scan_kernel(const float* __restrict__ xc,
                 const float* __restrict__ bc,     // [NROWS][32]
                 const float* __restrict__ A_log,  // [DINNER][16]
                 const float* __restrict__ Dvec,
                 const float* __restrict__ xz,
                 const float* __restrict__ Wdt,    // [16, DINNER]
                 const float* __restrict__ bdt,
                 float* __restrict__ g)
{
    int gid = blockIdx.x * blockDim.x + threadIdx.x;   // BATCH*DINNER*4
    int j   = gid & 3;                  // lane in 4-group
    int ch  = gid >> 2;
    int d   = ch & (DINNER - 1);
    int b   = ch >> 11;
    int s0  = 4 * j;

    float4 al = *(const float4*)&A_log[d * DSTATE + s0];
    const float a0 = -expf(al.x);
    const float a1 = -expf(al.y);
    const float a2 = -expf(al.z);
    const float a3 = -expf(al.w);
    const float Dd    = Dvec[d];
    const float wdt0  = Wdt[(s0 + 0) * DINNER + d];
    const float wdt1  = Wdt[(s0 + 1) * DINNER + d];
    const float wdt2  = Wdt[(s0 + 2) * DINNER + d];
    const float wdt3  = Wdt[(s0 + 3) * DINNER + d];
    const float bdt_d = bdt[d];

    const float* xptr = xc + (size_t)b * SEQL * DINNER + d;
    const float* zptr = xz + (size_t)b * SEQL * (2 * DINNER) + DINNER + d;
    const float* bcb  = bc + (size_t)b * SEQL * 32;
    float*       gptr = g  + (size_t)b * SEQL * DINNER + kperm_pos(d);

    float h0 = 0.f, h1 = 0.f, h2 = 0.f, h3 = 0.f;
    for (int l0 = 0; l0 < SEQL; l0 += UNR) {
        float  bxt[UNR], bzv[UNR];
        float4 bB[UNR], bC[UNR];
        #pragma unroll
        for (int i = 0; i < UNR; i++) {
            bxt[i] = xptr[(size_t)(l0 + i) * DINNER];
            bzv[i] = zptr[(size_t)(l0 + i) * (2 * DINNER)];
            bB[i]  = *(const float4*)&bcb[(l0 + i) * 32 + s0];
            bC[i]  = *(const float4*)&bcb[(l0 + i) * 32 + 16 + s0];
        }
        // phase A: deltas + decay factors (independent across i -> ILP)
        float dA0[UNR], dA1[UNR], dA2[UNR], dA3[UNR];
        float w0[UNR], w1[UNR], w2[UNR], w3[UNR];
        #pragma unroll
        for (int i = 0; i < UNR; i++) {
            float pd = fmaf(bB[i].x, wdt0,
                       fmaf(bB[i].y, wdt1,
                       fmaf(bB[i].z, wdt2, bB[i].w * wdt3)));
            pd += __shfl_xor_sync(0xffffffffu, pd, 1);
            pd += __shfl_xor_sync(0xffffffffu, pd, 2);
            float dl  = pd + bdt_d;
            float dtv = (dl > 20.f) ? dl : __logf(1.f + __expf(dl));
            dA0[i] = __expf(dtv * a0);
            dA1[i] = __expf(dtv * a1);
            dA2[i] = __expf(dtv * a2);
            dA3[i] = __expf(dtv * a3);
            float dx = dtv * bxt[i];
            w0[i] = dx * bB[i].x;
            w1[i] = dx * bB[i].y;
            w2[i] = dx * bB[i].z;
            w3[i] = dx * bB[i].w;
        }
        // phase B: the recurrences — four interleaved FMA chains
        float p[UNR];
        #pragma unroll
        for (int i = 0; i < UNR; i++) {
            h0 = fmaf(dA0[i], h0, w0[i]);
            h1 = fmaf(dA1[i], h1, w1[i]);
            h2 = fmaf(dA2[i], h2, w2[i]);
            h3 = fmaf(dA3[i], h3, w3[i]);
            p[i] = fmaf(h0, bC[i].x, fmaf(h1, bC[i].y, fmaf(h2, bC[i].z, h3 * bC[i].w)));
        }
        // phase C: output reductions (independent -> ILP)
        #pragma unroll
        for (int i = 0; i < UNR; i++) {
            p[i] += __shfl_xor_sync(0xffffffffu, p[i], 1);
            p[i] += __shfl_xor_sync(0xffffffffu, p[i], 2);
        }
        if (j == 0) {
            #pragma unroll
            for (int i = 0; i < UNR; i++) {
                float y   = fmaf(Dd, bxt[i], p[i]);
                float z   = bzv[i];
                float sig = 1.f / (1.f + __expf(-z));
                gptr[(size_t)(l0 + i) * DINNER] = round_tf32(y * (z * sig));
            }
        }
    }
}

// ---------------- launch ----------------
extern "C" void kernel_launch(void* const* d_in, const int* in_sizes, int n_in,
                              void* d_out, int out_size)
{
    const float* x      = (const float*)d_in[0];
    const float* W_in   = (const float*)d_in[1];
    const float* conv_w = (const float*)d_in[2];
    const float* conv_b = (const float*)d_in[3];
    const float* W_xprj = (const float*)d_in[4];
    const float* W_dt   = (const float*)d_in[5];
    const float* b_dt   = (const float*)d_in[6];
    const float* A_log  = (const float*)d_in[7];
    const float* Dvec   = (const float*)d_in[8];
    const float* W_out  = (const float*)d_in[9];
    float* out = (float*)d_out;

    float *xz, *xc, *bc, *gg, *xr, *wt_in, *wt_out;
    cudaGetSymbolAddress((void**)&xz, g_xz);
    cudaGetSymbolAddress((void**)&xc, g_xc);
    cudaGetSymbolAddress((void**)&bc, g_bc);
    cudaGetSymbolAddress((void**)&gg, g_gg);
    cudaGetSymbolAddress((void**)&xr, g_xr);
    cudaGetSymbolAddress((void**)&wt_in, g_wt_in);
    cudaGetSymbolAddress((void**)&wt_out, g_wt_out);

    // 0) preprocess operands: round to tf32, transpose weights to [N,K], permute K
    {
        int n8 = (NROWS * DMODEL) / 8;
        round_perm_kernel<<<(n8 + 255) / 256, 256>>>(x, xr, n8);
        dim3 blk(32, 8);
        transpose_rp_kernel<<<dim3((2 * DINNER) / 32, DMODEL / 32), blk>>>(W_in, wt_in, DMODEL, 2 * DINNER);
        transpose_rp_kernel<<<dim3(DMODEL / 32, DINNER / 32), blk>>>(W_out, wt_out, DINNER, DMODEL);
    }
    // 1) xz = x @ W_in   (M=4096, N=4096, K=1024), 128-row tiles
    {
        dim3 grid((2 * DINNER) / 128, NROWS / 128);
        tf32gemm_kernel<128><<<grid, 128>>>(xr, wt_in, xz, NROWS, 2 * DINNER, DMODEL);
    }
    // 2) conv + SiLU
    {
        int total = NROWS * DINNER;
        conv_silu_kernel<<<(total + 255) / 256, 256>>>(xz, conv_w, conv_b, xc);
    }
    // 3) BC = xc @ W_xproj
    xproj_kernel<<<NROWS / 4, 256>>>(xc, W_xprj, bc);
    // 4) scan (delta fused, +D, +gate, tf32 + K-permuted output), 4 lanes/channel
    {
        int total = BATCH * DINNER * 4;   // 16384
        scan_kernel<<<total / 256, 256>>>(xc, bc, A_log, Dvec, xz, W_dt, b_dt, gg);
    }
    // 5) out = g @ W_out  (M=4096, N=1024, K=2048), 64-row tiles for 512 CTAs
    {
        dim3 grid(DMODEL / 128, NROWS / 64);
        tf32gemm_kernel<64><<<grid, 128>>>(gg, wt_out, out, NROWS, DMODEL, DINNER);
    }
}